// round 6
// baseline (speedup 1.0000x reference)
#include <cuda_runtime.h>
#include <cuda_bf16.h>
#include <math_constants.h>

#define BATCH    1024
#define NHID     1024
#define NCLASSES 224
#define NPC      225
#define DSEG     8
#define DLEN     128      // NHID / DSEG
#define SCH      8        // samples per chunk (bottom)
#define KSEG     8        // split-K for top gemm
#define KLEN     128      // NHID / KSEG
#define TROWS    64       // rows per top-gemm block (8 warps x 8 rows)

// ---------------- scratch (device globals) ----------------------------------
__device__ float g_top_logits[BATCH * NCLASSES];
__device__ float g_bot_logits[BATCH * NPC];
__device__ int   g_pos_top[BATCH];
__device__ int   g_pos_bottom[BATCH];
__device__ int   g_count[NCLASSES];
__device__ int   g_offset[NCLASSES + 1];
__device__ int   g_sorted[BATCH];

// ---------------- 0: zero logit accumulators ---------------------------------
__global__ void __launch_bounds__(256) k_zero()
{
    int i = blockIdx.x * blockDim.x + threadIdx.x;
    int N1 = BATCH * NCLASSES;          // 229376
    int N2 = BATCH * NPC;               // 230400
    int stride = gridDim.x * blockDim.x;
    for (int j = i; j < N1; j += stride) g_top_logits[j] = 0.f;
    for (int j = i; j < N2; j += stride) g_bot_logits[j] = 0.f;
}

// ---------------- 1: prep — decode labels, histogram, scan, scatter ---------
__global__ void __launch_bounds__(1024) k_prep(const void* __restrict__ labels_raw)
{
    __shared__ int s_count[NCLASSES];
    __shared__ int s_off[NCLASSES];
    int t = threadIdx.x;   // 1024 threads, one per sample

    if (t < NCLASSES) s_count[t] = 0;
    __syncthreads();

    // detect int64 vs int32 labels (odd 32-bit words all zero => int64 LE)
    const unsigned int* w = (const unsigned int*)labels_raw;
    bool is64 = ((w[1] | w[3] | w[5] | w[7] | w[9] | w[11] | w[13] | w[15]) == 0u);
    long long lab = is64 ? ((const long long*)labels_raw)[t]
                         : (long long)(((const int*)labels_raw)[t]);
    int pt = (int)(lab / NPC);
    int pb = (int)(lab % NPC);
    g_pos_top[t]    = pt;
    g_pos_bottom[t] = pb;
    atomicAdd(&s_count[pt], 1);
    __syncthreads();

    // warp 0: exclusive scan of 224 counts
    if (t < 32) {
        int base = t * 7;
        int v[7], loc[7];
        int sum = 0;
#pragma unroll
        for (int i = 0; i < 7; i++) v[i] = s_count[base + i];
#pragma unroll
        for (int i = 0; i < 7; i++) { loc[i] = sum; sum += v[i]; }
        int run = sum;
#pragma unroll
        for (int o = 1; o < 32; o <<= 1) {
            int nb = __shfl_up_sync(0xFFFFFFFFu, run, o);
            if (t >= o) run += nb;
        }
        int excl = run - sum;
#pragma unroll
        for (int i = 0; i < 7; i++) {
            s_off[base + i]    = excl + loc[i];
            g_offset[base + i] = excl + loc[i];
        }
        if (t == 31) g_offset[NCLASSES] = excl + sum;
    }
    __syncthreads();
    if (t < NCLASSES) g_count[t] = s_count[t];

    int p = atomicAdd(&s_off[pt], 1);
    g_sorted[p] = t;
}

// ---------------- 2: top GEMM (split-K, atomic epilogue) ----------------------
// grid (16 rowgroups, 8 ksegs) = 128 blocks (one wave); 8 warps x 8 rows each.
__global__ void __launch_bounds__(256) k_top(
    const float* __restrict__ X,
    const float* __restrict__ Wt)    // [NHID, NCLASSES]
{
    int r0 = blockIdx.x * TROWS;
    int k0 = blockIdx.y * KLEN;
    int t = threadIdx.x, warp = t >> 5, lane = t & 31;

    __shared__ float Xs[TROWS][KLEN];      // 32 KB
    __shared__ float Ws[16][NCLASSES];     // 14.3 KB

    // stage X tile (64 rows x 128 k), float4 coalesced
    for (int i = t; i < TROWS * 32; i += 256) {
        int r = i >> 5, q = i & 31;
        const float4* src = (const float4*)(X + (size_t)(r0 + r) * NHID + k0);
        ((float4*)&Xs[r][0])[q] = src[q];
    }

    float acc[8][7];
#pragma unroll
    for (int r = 0; r < 8; r++)
#pragma unroll
        for (int i = 0; i < 7; i++) acc[r][i] = 0.f;

    for (int kc = 0; kc < KLEN; kc += 16) {
        __syncthreads();
        for (int i = t; i < 16 * NCLASSES; i += 256) {
            int kk = i / NCLASSES;
            int c  = i - kk * NCLASSES;
            Ws[kk][c] = Wt[(size_t)(k0 + kc + kk) * NCLASSES + c];
        }
        __syncthreads();
#pragma unroll
        for (int kq = 0; kq < 16; kq += 4) {
            // broadcast X values via LDS.128 (4 k per wavefront per row)
            float4 xv[8];
#pragma unroll
            for (int r = 0; r < 8; r++)
                xv[r] = *(const float4*)&Xs[warp * 8 + r][kc + kq];
            const float* xf = (const float*)xv;
#pragma unroll
            for (int j = 0; j < 4; j++) {
#pragma unroll
                for (int i = 0; i < 7; i++) {
                    float wv = Ws[kq + j][lane + 32 * i];
#pragma unroll
                    for (int r = 0; r < 8; r++)
                        acc[r][i] += xf[r * 4 + j] * wv;
                }
            }
        }
    }

#pragma unroll
    for (int r = 0; r < 8; r++) {
        int row = r0 + warp * 8 + r;
#pragma unroll
        for (int i = 0; i < 7; i++)
            atomicAdd(&g_top_logits[row * NCLASSES + lane + 32 * i], acc[r][i]);
    }
}

// ---------------- 3: bottom split-D (2 cols/thread, LDS.128 X) ---------------
// grid (224 classes, 8 d-segments); block 128 = 4 warps; warp w covers cols
// [64w, 64w+64): lane l owns cols 64w+l and 64w+32+l.
__global__ void __launch_bounds__(128) k_bottom(
    const float* __restrict__ X,
    const float* __restrict__ Wb)    // [NCLASSES, NHID, NPC]
{
    int c   = blockIdx.x;
    int seg = blockIdx.y;
    int n = g_count[c];
    if (n == 0) return;
    int base = g_offset[c];
    int d0   = seg * DLEN;
    int t = threadIdx.x, warp = t >> 5, lane = t & 31;

    int c0 = warp * 64 + lane;
    int c1 = c0 + 32;
    bool v0 = (c0 < NPC), v1 = (c1 < NPC);

    __shared__ float Xs[SCH][DLEN];    // 4 KB
    __shared__ int   ids[SCH];

    const float* W = Wb + (size_t)c * NHID * NPC + (size_t)d0 * NPC;

    for (int s0 = 0; s0 < n; s0 += SCH) {
        int ns = min(SCH, n - s0);
        __syncthreads();
        if (t < ns) ids[t] = g_sorted[base + s0 + t];
        __syncthreads();

        // stage X rows (float4 coalesced), zero-fill unused sample slots
        for (int i = t; i < SCH * 32; i += 128) {
            int s = i >> 5, q = i & 31;
            float4 val = make_float4(0.f, 0.f, 0.f, 0.f);
            if (s < ns)
                val = ((const float4*)(X + (size_t)ids[s] * NHID + d0))[q];
            ((float4*)&Xs[s][0])[q] = val;
        }
        __syncthreads();

        float acc0[SCH], acc1[SCH];
#pragma unroll
        for (int s = 0; s < SCH; s++) { acc0[s] = 0.f; acc1[s] = 0.f; }

#pragma unroll 2
        for (int dq = 0; dq < DLEN; dq += 4) {
            float w0[4], w1[4];
            const float* Wd = W + (size_t)dq * NPC;
#pragma unroll
            for (int k = 0; k < 4; k++) {
                w0[k] = v0 ? __ldg(Wd + (size_t)k * NPC + c0) : 0.f;
                w1[k] = v1 ? __ldg(Wd + (size_t)k * NPC + c1) : 0.f;
            }
#pragma unroll
            for (int s = 0; s < SCH; s++) {
                float4 x = *(const float4*)&Xs[s][dq];
                acc0[s] += x.x * w0[0]; acc1[s] += x.x * w1[0];
                acc0[s] += x.y * w0[1]; acc1[s] += x.y * w1[1];
                acc0[s] += x.z * w0[2]; acc1[s] += x.z * w1[2];
                acc0[s] += x.w * w0[3]; acc1[s] += x.w * w1[3];
            }
        }

        for (int s = 0; s < ns; s++) {
            int sid = ids[s];
            if (v0) atomicAdd(&g_bot_logits[sid * NPC + c0], acc0[s]);
            if (v1) atomicAdd(&g_bot_logits[sid * NPC + c1], acc1[s]);
        }
    }
}

// ---------------- 4: fused finish — both softmaxes + output ------------------
// one warp per sample
__global__ void __launch_bounds__(256) k_finish(
    const float* __restrict__ bt,   // [224]
    const float* __restrict__ bb,   // [NCLASSES, NPC]
    float* __restrict__ out)
{
    int sid  = (blockIdx.x * blockDim.x + threadIdx.x) >> 5;
    int lane = threadIdx.x & 31;
    if (sid >= BATCH) return;
    int c = g_pos_top[sid];

    // ---- top softmax over 224 classes (7 per lane) ----
    float lt[7];
    float mx = -CUDART_INF_F;
#pragma unroll
    for (int i = 0; i < 7; i++) {
        int cc = lane + 32 * i;
        lt[i] = g_top_logits[sid * NCLASSES + cc] + bt[cc];
        mx = fmaxf(mx, lt[i]);
    }
#pragma unroll
    for (int o = 16; o > 0; o >>= 1) mx = fmaxf(mx, __shfl_xor_sync(0xFFFFFFFFu, mx, o));
    float s = 0.f;
#pragma unroll
    for (int i = 0; i < 7; i++) s += __expf(lt[i] - mx);
#pragma unroll
    for (int o = 16; o > 0; o >>= 1) s += __shfl_xor_sync(0xFFFFFFFFu, s, o);

    float myv  = lt[c >> 5];
    float tgt  = __shfl_sync(0xFFFFFFFFu, myv, c & 31);
    float top_p = __expf(tgt - mx) / s;

    // ---- bottom softmax over 225 columns (8 per lane, last partial) ----
    float vb[8];
    float mxb = -CUDART_INF_F;
#pragma unroll
    for (int k = 0; k < 8; k++) {
        int col = lane + 32 * k;
        if (col < NPC) {
            vb[k] = g_bot_logits[sid * NPC + col] + bb[c * NPC + col];
            mxb = fmaxf(mxb, vb[k]);
        } else vb[k] = -CUDART_INF_F;
    }
#pragma unroll
    for (int o = 16; o > 0; o >>= 1) mxb = fmaxf(mxb, __shfl_xor_sync(0xFFFFFFFFu, mxb, o));
    float sb = 0.f;
#pragma unroll
    for (int k = 0; k < 8; k++) sb += __expf(vb[k] - mxb);
#pragma unroll
    for (int o = 16; o > 0; o >>= 1) sb += __shfl_xor_sync(0xFFFFFFFFu, sb, o);

    int pb = g_pos_bottom[sid];
    if (lane == (pb & 31))
        out[sid] = top_p * (__expf(vb[pb >> 5] - mxb) / sb);
}

// ---------------- launch -----------------------------------------------------
extern "C" void kernel_launch(void* const* d_in, const int* in_sizes, int n_in,
                              void* d_out, int out_size)
{
    const float* X   = (const float*)d_in[0];   // [1024, 1024]
    const void*  lab = d_in[1];                 // [1024] int32/int64
    const float* Wt  = (const float*)d_in[2];   // [1024, 224]
    const float* bt  = (const float*)d_in[3];   // [224]
    const float* Wb  = (const float*)d_in[4];   // [224, 1024, 225]
    const float* bb  = (const float*)d_in[5];   // [224, 225]
    float* out = (float*)d_out;

    k_zero<<<448, 256>>>();
    k_prep<<<1, 1024>>>(lab);
    k_top<<<dim3(BATCH / TROWS, KSEG), 256>>>(X, Wt);
    k_bottom<<<dim3(NCLASSES, DSEG), 128>>>(X, Wb);
    k_finish<<<BATCH / 8, 256>>>(bt, bb, out);
}

// round 7
// speedup vs baseline: 1.1516x; 1.1516x over previous
#include <cuda_runtime.h>
#include <cuda_bf16.h>
#include <math_constants.h>

#define BATCH    1024
#define NHID     1024
#define NCLASSES 224
#define NPC      225
#define DSEG     8
#define DLEN     128      // NHID / DSEG
#define SCH      8        // samples per chunk (bottom)
#define KSEG     8        // split-K segments for top gemm
#define KLEN     128      // NHID / KSEG
#define BOT_BLOCKS (NCLASSES * DSEG)          // 1792
#define TOP_ROWG   64                          // rowgroups of 16 rows
#define TOP_BLOCKS (TOP_ROWG * KSEG)           // 512

// ---------------- scratch (device globals) ----------------------------------
__device__ float g_top_logits[BATCH * NCLASSES];
__device__ float g_bot_logits[BATCH * NPC];
__device__ int   g_pos_top[BATCH];
__device__ int   g_pos_bottom[BATCH];
__device__ int   g_count[NCLASSES];
__device__ int   g_offset[NCLASSES + 1];
__device__ int   g_sorted[BATCH];

// ---------------- 1: init — zero accumulators + (block 0) label prep --------
__global__ void __launch_bounds__(1024) k_init(const void* __restrict__ labels_raw)
{
    int t = threadIdx.x;

    if (blockIdx.x == 0) {
        __shared__ int s_count[NCLASSES];
        __shared__ int s_off[NCLASSES];
        if (t < NCLASSES) s_count[t] = 0;
        __syncthreads();

        // detect int64 vs int32 labels (odd 32-bit words all zero => int64 LE)
        const unsigned int* w = (const unsigned int*)labels_raw;
        bool is64 = ((w[1] | w[3] | w[5] | w[7] | w[9] | w[11] | w[13] | w[15]) == 0u);
        long long lab = is64 ? ((const long long*)labels_raw)[t]
                             : (long long)(((const int*)labels_raw)[t]);
        int pt = (int)(lab / NPC);
        int pb = (int)(lab % NPC);
        g_pos_top[t]    = pt;
        g_pos_bottom[t] = pb;
        atomicAdd(&s_count[pt], 1);
        __syncthreads();

        if (t < 32) {
            int base = t * 7;
            int v[7], loc[7];
            int sum = 0;
#pragma unroll
            for (int i = 0; i < 7; i++) v[i] = s_count[base + i];
#pragma unroll
            for (int i = 0; i < 7; i++) { loc[i] = sum; sum += v[i]; }
            int run = sum;
#pragma unroll
            for (int o = 1; o < 32; o <<= 1) {
                int nb = __shfl_up_sync(0xFFFFFFFFu, run, o);
                if (t >= o) run += nb;
            }
            int excl = run - sum;
#pragma unroll
            for (int i = 0; i < 7; i++) {
                s_off[base + i]    = excl + loc[i];
                g_offset[base + i] = excl + loc[i];
            }
            if (t == 31) g_offset[NCLASSES] = excl + sum;
        }
        __syncthreads();
        if (t < NCLASSES) g_count[t] = s_count[t];
        int p = atomicAdd(&s_off[pt], 1);
        g_sorted[p] = t;
    }

    // all blocks: zero logit accumulators
    int i = blockIdx.x * 1024 + t;
    int stride = gridDim.x * 1024;
    for (int j = i; j < BATCH * NCLASSES; j += stride) g_top_logits[j] = 0.f;
    for (int j = i; j < BATCH * NPC; j += stride)      g_bot_logits[j] = 0.f;
}

// ---------------- 2: fused main — bottom matvecs + top GEMM ------------------
// blocks [0, 1792): bottom (class c = bx/8, d-segment = bx%8)
// blocks [1792, 2304): top gemm (rowgroup of 16, k-segment of 128)
__global__ void __launch_bounds__(128) k_main(
    const float* __restrict__ X,    // [BATCH, NHID]
    const float* __restrict__ Wt,   // [NHID, NCLASSES]
    const float* __restrict__ Wb)   // [NCLASSES, NHID, NPC]
{
    __shared__ union {
        struct { float Xs[SCH][DLEN]; int ids[SCH]; } b;      // 4.1 KB
        struct { float Xs[16][KLEN]; float Ws[16][NCLASSES]; } tp; // 22.3 KB
    } sm;

    int bx = blockIdx.x;
    int t = threadIdx.x, warp = t >> 5, lane = t & 31;

    if (bx < BOT_BLOCKS) {
        // ===================== bottom =====================
        int c   = bx >> 3;
        int seg = bx & 7;
        int n = g_count[c];
        if (n == 0) return;
        int base = g_offset[c];
        int d0   = seg * DLEN;

        int c0 = warp * 64 + lane;
        int c1 = c0 + 32;
        bool v0 = (c0 < NPC), v1 = (c1 < NPC);

        const float* W = Wb + (size_t)c * NHID * NPC + (size_t)d0 * NPC;

        for (int s0 = 0; s0 < n; s0 += SCH) {
            int ns = min(SCH, n - s0);
            __syncthreads();
            if (t < ns) sm.b.ids[t] = g_sorted[base + s0 + t];
            __syncthreads();

            // stage X rows (float4 coalesced), zero-fill unused sample slots
            for (int i = t; i < SCH * 32; i += 128) {
                int s = i >> 5, q = i & 31;
                float4 val = make_float4(0.f, 0.f, 0.f, 0.f);
                if (s < ns)
                    val = ((const float4*)(X + (size_t)sm.b.ids[s] * NHID + d0))[q];
                ((float4*)&sm.b.Xs[s][0])[q] = val;
            }
            __syncthreads();

            float acc0[SCH], acc1[SCH];
#pragma unroll
            for (int s = 0; s < SCH; s++) { acc0[s] = 0.f; acc1[s] = 0.f; }

            for (int dq = 0; dq < DLEN; dq += 8) {
                float w0[8], w1[8];
                const float* Wd = W + (size_t)dq * NPC;
#pragma unroll
                for (int k = 0; k < 8; k++) {
                    w0[k] = v0 ? __ldg(Wd + (size_t)k * NPC + c0) : 0.f;
                    w1[k] = v1 ? __ldg(Wd + (size_t)k * NPC + c1) : 0.f;
                }
#pragma unroll
                for (int s = 0; s < SCH; s++) {
                    float4 xa = *(const float4*)&sm.b.Xs[s][dq];
                    float4 xb = *(const float4*)&sm.b.Xs[s][dq + 4];
                    acc0[s] += xa.x * w0[0]; acc1[s] += xa.x * w1[0];
                    acc0[s] += xa.y * w0[1]; acc1[s] += xa.y * w1[1];
                    acc0[s] += xa.z * w0[2]; acc1[s] += xa.z * w1[2];
                    acc0[s] += xa.w * w0[3]; acc1[s] += xa.w * w1[3];
                    acc0[s] += xb.x * w0[4]; acc1[s] += xb.x * w1[4];
                    acc0[s] += xb.y * w0[5]; acc1[s] += xb.y * w1[5];
                    acc0[s] += xb.z * w0[6]; acc1[s] += xb.z * w1[6];
                    acc0[s] += xb.w * w0[7]; acc1[s] += xb.w * w1[7];
                }
            }

            for (int s = 0; s < ns; s++) {
                int sid = sm.b.ids[s];
                if (v0) atomicAdd(&g_bot_logits[sid * NPC + c0], acc0[s]);
                if (v1) atomicAdd(&g_bot_logits[sid * NPC + c1], acc1[s]);
            }
        }
    } else {
        // ===================== top GEMM =====================
        int tb = bx - BOT_BLOCKS;
        int r0 = (tb >> 3) * 16;
        int k0 = (tb & 7) * KLEN;

        // stage X tile (16 rows x 128 k), float4 coalesced
        for (int i = t; i < 16 * 32; i += 128) {
            int r = i >> 5, q = i & 31;
            ((float4*)&sm.tp.Xs[r][0])[q] =
                ((const float4*)(X + (size_t)(r0 + r) * NHID + k0))[q];
        }

        float acc[4][7];
#pragma unroll
        for (int r = 0; r < 4; r++)
#pragma unroll
            for (int i = 0; i < 7; i++) acc[r][i] = 0.f;

        for (int kc = 0; kc < KLEN; kc += 16) {
            __syncthreads();
            for (int i = t; i < 16 * NCLASSES; i += 128) {
                int kk = i / NCLASSES;
                int cc = i - kk * NCLASSES;
                sm.tp.Ws[kk][cc] = Wt[(size_t)(k0 + kc + kk) * NCLASSES + cc];
            }
            __syncthreads();
#pragma unroll
            for (int kq = 0; kq < 16; kq += 4) {
                float4 xv[4];
#pragma unroll
                for (int r = 0; r < 4; r++)
                    xv[r] = *(const float4*)&sm.tp.Xs[warp * 4 + r][kc + kq];
                const float* xf = (const float*)xv;
#pragma unroll
                for (int j = 0; j < 4; j++) {
#pragma unroll
                    for (int i = 0; i < 7; i++) {
                        float wv = sm.tp.Ws[kq + j][lane + 32 * i];
#pragma unroll
                        for (int r = 0; r < 4; r++)
                            acc[r][i] += xf[r * 4 + j] * wv;
                    }
                }
            }
        }

#pragma unroll
        for (int r = 0; r < 4; r++) {
            int row = r0 + warp * 4 + r;
#pragma unroll
            for (int i = 0; i < 7; i++)
                atomicAdd(&g_top_logits[row * NCLASSES + lane + 32 * i], acc[r][i]);
        }
    }
}

// ---------------- 3: fused finish — both softmaxes + output ------------------
// one warp per sample
__global__ void __launch_bounds__(256) k_finish(
    const float* __restrict__ bt,   // [224]
    const float* __restrict__ bb,   // [NCLASSES, NPC]
    float* __restrict__ out)
{
    int sid  = (blockIdx.x * blockDim.x + threadIdx.x) >> 5;
    int lane = threadIdx.x & 31;
    if (sid >= BATCH) return;
    int c = g_pos_top[sid];

    // ---- top softmax over 224 classes (7 per lane) ----
    float lt[7];
    float mx = -CUDART_INF_F;
#pragma unroll
    for (int i = 0; i < 7; i++) {
        int cc = lane + 32 * i;
        lt[i] = g_top_logits[sid * NCLASSES + cc] + bt[cc];
        mx = fmaxf(mx, lt[i]);
    }
#pragma unroll
    for (int o = 16; o > 0; o >>= 1) mx = fmaxf(mx, __shfl_xor_sync(0xFFFFFFFFu, mx, o));
    float s = 0.f;
#pragma unroll
    for (int i = 0; i < 7; i++) s += __expf(lt[i] - mx);
#pragma unroll
    for (int o = 16; o > 0; o >>= 1) s += __shfl_xor_sync(0xFFFFFFFFu, s, o);

    float myv  = lt[c >> 5];
    float tgt  = __shfl_sync(0xFFFFFFFFu, myv, c & 31);
    float top_p = __expf(tgt - mx) / s;

    // ---- bottom softmax over 225 columns (8 per lane, last partial) ----
    float vb[8];
    float mxb = -CUDART_INF_F;
#pragma unroll
    for (int k = 0; k < 8; k++) {
        int col = lane + 32 * k;
        if (col < NPC) {
            vb[k] = g_bot_logits[sid * NPC + col] + bb[c * NPC + col];
            mxb = fmaxf(mxb, vb[k]);
        } else vb[k] = -CUDART_INF_F;
    }
#pragma unroll
    for (int o = 16; o > 0; o >>= 1) mxb = fmaxf(mxb, __shfl_xor_sync(0xFFFFFFFFu, mxb, o));
    float sb = 0.f;
#pragma unroll
    for (int k = 0; k < 8; k++) sb += __expf(vb[k] - mxb);
#pragma unroll
    for (int o = 16; o > 0; o >>= 1) sb += __shfl_xor_sync(0xFFFFFFFFu, sb, o);

    int pb = g_pos_bottom[sid];
    if (lane == (pb & 31))
        out[sid] = top_p * (__expf(vb[pb >> 5] - mxb) / sb);
}

// ---------------- launch -----------------------------------------------------
extern "C" void kernel_launch(void* const* d_in, const int* in_sizes, int n_in,
                              void* d_out, int out_size)
{
    const float* X   = (const float*)d_in[0];   // [1024, 1024]
    const void*  lab = d_in[1];                 // [1024] int32/int64
    const float* Wt  = (const float*)d_in[2];   // [1024, 224]
    const float* bt  = (const float*)d_in[3];   // [224]
    const float* Wb  = (const float*)d_in[4];   // [224, 1024, 225]
    const float* bb  = (const float*)d_in[5];   // [224, 225]
    float* out = (float*)d_out;

    k_init<<<112, 1024>>>(lab);
    k_main<<<BOT_BLOCKS + TOP_BLOCKS, 128>>>(X, Wt, Wb);
    k_finish<<<BATCH / 8, 256>>>(bt, bb, out);
}

// round 8
// speedup vs baseline: 1.3313x; 1.1561x over previous
#include <cuda_runtime.h>
#include <cuda_bf16.h>
#include <math_constants.h>
#include <cstdint>

#define BATCH    1024
#define NHID     1024
#define NCLASSES 224
#define NPC      225
#define DSEG     8
#define DLEN     128      // NHID / DSEG
#define SCH      8        // samples per chunk (bottom)
#define KSEG     8        // split-K segments for top gemm
#define KLEN     128      // NHID / KSEG
#define TD       16       // d-rows per cp.async weight tile
#define NTILE    (DLEN / TD)                   // 8
#define BOT_BLOCKS (NCLASSES * DSEG)           // 1792
#define TOP_BLOCKS 512                         // 64 rowgroups x 8 ksegs
#define ALL_BLOCKS (BOT_BLOCKS + TOP_BLOCKS)   // 2304

// ---------------- scratch (device globals) ----------------------------------
__device__ float g_top_logits[BATCH * NCLASSES];
__device__ float g_bot_logits[BATCH * NPC];
__device__ int   g_pos_top[BATCH];
__device__ int   g_pos_bottom[BATCH];
__device__ int   g_count[NCLASSES];
__device__ int   g_offset[NCLASSES + 1];
__device__ int   g_sorted[BATCH];

// ---------------- cp.async helpers ------------------------------------------
__device__ __forceinline__ void cp16(uint32_t dst_smem, const void* src) {
    asm volatile("cp.async.cg.shared.global [%0], [%1], 16;"
                 :: "r"(dst_smem), "l"(src));
}
__device__ __forceinline__ void cp_commit() {
    asm volatile("cp.async.commit_group;");
}
__device__ __forceinline__ void cp_wait1() {
    asm volatile("cp.async.wait_group 1;");
}

// ---------------- 1: init — zero accumulators + (block 0) label prep --------
__global__ void __launch_bounds__(1024) k_init(const void* __restrict__ labels_raw)
{
    int t = threadIdx.x;

    if (blockIdx.x == 0) {
        __shared__ int s_count[NCLASSES];
        __shared__ int s_off[NCLASSES];
        if (t < NCLASSES) s_count[t] = 0;
        __syncthreads();

        // detect int64 vs int32 labels (odd 32-bit words all zero => int64 LE)
        const unsigned int* w = (const unsigned int*)labels_raw;
        bool is64 = ((w[1] | w[3] | w[5] | w[7] | w[9] | w[11] | w[13] | w[15]) == 0u);
        long long lab = is64 ? ((const long long*)labels_raw)[t]
                             : (long long)(((const int*)labels_raw)[t]);
        int pt = (int)(lab / NPC);
        int pb = (int)(lab % NPC);
        g_pos_top[t]    = pt;
        g_pos_bottom[t] = pb;
        atomicAdd(&s_count[pt], 1);
        __syncthreads();

        if (t < 32) {
            int base = t * 7;
            int v[7], loc[7];
            int sum = 0;
#pragma unroll
            for (int i = 0; i < 7; i++) v[i] = s_count[base + i];
#pragma unroll
            for (int i = 0; i < 7; i++) { loc[i] = sum; sum += v[i]; }
            int run = sum;
#pragma unroll
            for (int o = 1; o < 32; o <<= 1) {
                int nb = __shfl_up_sync(0xFFFFFFFFu, run, o);
                if (t >= o) run += nb;
            }
            int excl = run - sum;
#pragma unroll
            for (int i = 0; i < 7; i++) {
                s_off[base + i]    = excl + loc[i];
                g_offset[base + i] = excl + loc[i];
            }
            if (t == 31) g_offset[NCLASSES] = excl + sum;
        }
        __syncthreads();
        if (t < NCLASSES) g_count[t] = s_count[t];
        int p = atomicAdd(&s_off[pt], 1);
        g_sorted[p] = t;
    }

    int i = blockIdx.x * 1024 + t;
    int stride = gridDim.x * 1024;
    for (int j = i; j < BATCH * NCLASSES; j += stride) g_top_logits[j] = 0.f;
    for (int j = i; j < BATCH * NPC; j += stride)      g_bot_logits[j] = 0.f;
}

// ---------------- 2: fused main — bottom (cp.async W) + top GEMM -------------
// bids interleaved: per group of 9, 7 bottom + 2 top (r==4, r==8).
__global__ void __launch_bounds__(128) k_main(
    const float* __restrict__ X,    // [BATCH, NHID]
    const float* __restrict__ Wt,   // [NHID, NCLASSES]
    const float* __restrict__ Wb)   // [NCLASSES, NHID, NPC]
{
    __shared__ __align__(16) union {
        struct {
            float Wsm[2][TD * NPC];   // 2 x 14.4 KB
            float Xs[SCH][DLEN];      // 4 KB
            int   ids[SCH];
        } b;
        struct { float Xs[16][KLEN]; float Ws[16][NCLASSES]; } tp;
    } sm;

    int bx = blockIdx.x;
    int g  = bx / 9;
    int r  = bx - g * 9;
    bool is_top = (r == 4) || (r == 8);
    int t = threadIdx.x, warp = t >> 5, lane = t & 31;

    if (!is_top) {
        // ===================== bottom =====================
        int bb_idx = g * 7 + (r < 4 ? r : r - 1);
        int c   = bb_idx >> 3;
        int seg = bb_idx & 7;
        int n = g_count[c];
        if (n == 0) return;
        int base = g_offset[c];
        int d0   = seg * DLEN;

        int c0 = warp * 64 + lane;          // always < 224
        int c1 = c0 + 32;
        bool v1 = (c1 < NPC);
        int c1c = v1 ? c1 : 224;

        const float* W = Wb + (size_t)c * NHID * NPC + (size_t)d0 * NPC;
        uint32_t smW0 = (uint32_t)__cvta_generic_to_shared(&sm.b.Wsm[0][0]);
        uint32_t smW1 = (uint32_t)__cvta_generic_to_shared(&sm.b.Wsm[1][0]);

        for (int s0 = 0; s0 < n; s0 += SCH) {
            int ns = min(SCH, n - s0);
            __syncthreads();
            if (t < ns) sm.b.ids[t] = g_sorted[base + s0 + t];
            __syncthreads();

            // stage X rows (float4 coalesced), zero-fill unused sample slots
            for (int i = t; i < SCH * 32; i += 128) {
                int s = i >> 5, q = i & 31;
                float4 val = make_float4(0.f, 0.f, 0.f, 0.f);
                if (s < ns)
                    val = ((const float4*)(X + (size_t)sm.b.ids[s] * NHID + d0))[q];
                ((float4*)&sm.b.Xs[s][0])[q] = val;
            }

            // prefetch weight tile 0 (TD*NPC floats = 900 float4, contiguous)
            {
                const float4* src = (const float4*)W;
                for (int i = t; i < TD * NPC / 4; i += 128)
                    cp16(smW0 + i * 16, src + i);
                cp_commit();
            }

            float acc0[SCH], acc1[SCH];
#pragma unroll
            for (int s = 0; s < SCH; s++) { acc0[s] = 0.f; acc1[s] = 0.f; }

            for (int tile = 0; tile < NTILE; tile++) {
                // prefetch next tile into the other buffer
                if (tile + 1 < NTILE) {
                    const float4* src = (const float4*)(W + (size_t)(tile + 1) * TD * NPC);
                    uint32_t dst = ((tile + 1) & 1) ? smW1 : smW0;
                    for (int i = t; i < TD * NPC / 4; i += 128)
                        cp16(dst + i * 16, src + i);
                }
                cp_commit();
                cp_wait1();
                __syncthreads();

                const float* Wsm = sm.b.Wsm[tile & 1];
                int tbase = tile * TD;
#pragma unroll
                for (int dq = 0; dq < TD; dq += 4) {
                    float w0[4], w1[4];
#pragma unroll
                    for (int k = 0; k < 4; k++) {
                        w0[k] = Wsm[(dq + k) * NPC + c0];
                        w1[k] = Wsm[(dq + k) * NPC + c1c];
                    }
#pragma unroll
                    for (int s = 0; s < SCH; s++) {
                        float4 x = *(const float4*)&sm.b.Xs[s][tbase + dq];
                        acc0[s] += x.x * w0[0]; acc1[s] += x.x * w1[0];
                        acc0[s] += x.y * w0[1]; acc1[s] += x.y * w1[1];
                        acc0[s] += x.z * w0[2]; acc1[s] += x.z * w1[2];
                        acc0[s] += x.w * w0[3]; acc1[s] += x.w * w1[3];
                    }
                }
                __syncthreads();   // protect buffer before next overwrite
            }

            for (int s = 0; s < ns; s++) {
                int sid = sm.b.ids[s];
                atomicAdd(&g_bot_logits[sid * NPC + c0], acc0[s]);
                if (v1) atomicAdd(&g_bot_logits[sid * NPC + c1], acc1[s]);
            }
        }
    } else {
        // ===================== top GEMM =====================
        int tb = g * 2 + (r == 8 ? 1 : 0);
        int r0 = (tb >> 3) * 16;
        int k0 = (tb & 7) * KLEN;

        for (int i = t; i < 16 * 32; i += 128) {
            int rr = i >> 5, q = i & 31;
            ((float4*)&sm.tp.Xs[rr][0])[q] =
                ((const float4*)(X + (size_t)(r0 + rr) * NHID + k0))[q];
        }

        float acc[4][7];
#pragma unroll
        for (int rr = 0; rr < 4; rr++)
#pragma unroll
            for (int i = 0; i < 7; i++) acc[rr][i] = 0.f;

        for (int kc = 0; kc < KLEN; kc += 16) {
            __syncthreads();
            for (int i = t; i < 16 * NCLASSES; i += 128) {
                int kk = i / NCLASSES;
                int cc = i - kk * NCLASSES;
                sm.tp.Ws[kk][cc] = Wt[(size_t)(k0 + kc + kk) * NCLASSES + cc];
            }
            __syncthreads();
#pragma unroll
            for (int kq = 0; kq < 16; kq += 4) {
                float4 xv[4];
#pragma unroll
                for (int rr = 0; rr < 4; rr++)
                    xv[rr] = *(const float4*)&sm.tp.Xs[warp * 4 + rr][kc + kq];
                const float* xf = (const float*)xv;
#pragma unroll
                for (int j = 0; j < 4; j++) {
#pragma unroll
                    for (int i = 0; i < 7; i++) {
                        float wv = sm.tp.Ws[kq + j][lane + 32 * i];
#pragma unroll
                        for (int rr = 0; rr < 4; rr++)
                            acc[rr][i] += xf[rr * 4 + j] * wv;
                    }
                }
            }
        }

#pragma unroll
        for (int rr = 0; rr < 4; rr++) {
            int row = r0 + warp * 4 + rr;
#pragma unroll
            for (int i = 0; i < 7; i++)
                atomicAdd(&g_top_logits[row * NCLASSES + lane + 32 * i], acc[rr][i]);
        }
    }
}

// ---------------- 3: fused finish — both softmaxes + output ------------------
// one warp per sample; 256 blocks x 128 threads
__global__ void __launch_bounds__(128) k_finish(
    const float* __restrict__ bt,   // [224]
    const float* __restrict__ bb,   // [NCLASSES, NPC]
    float* __restrict__ out)
{
    int sid  = (blockIdx.x * blockDim.x + threadIdx.x) >> 5;
    int lane = threadIdx.x & 31;
    if (sid >= BATCH) return;
    int c = g_pos_top[sid];

    // ---- top softmax over 224 classes (7 per lane) ----
    float lt[7];
    float mx = -CUDART_INF_F;
#pragma unroll
    for (int i = 0; i < 7; i++) {
        int cc = lane + 32 * i;
        lt[i] = g_top_logits[sid * NCLASSES + cc] + bt[cc];
        mx = fmaxf(mx, lt[i]);
    }
#pragma unroll
    for (int o = 16; o > 0; o >>= 1) mx = fmaxf(mx, __shfl_xor_sync(0xFFFFFFFFu, mx, o));
    float s = 0.f;
#pragma unroll
    for (int i = 0; i < 7; i++) s += __expf(lt[i] - mx);
#pragma unroll
    for (int o = 16; o > 0; o >>= 1) s += __shfl_xor_sync(0xFFFFFFFFu, s, o);

    float myv  = lt[c >> 5];
    float tgt  = __shfl_sync(0xFFFFFFFFu, myv, c & 31);
    float top_p = __expf(tgt - mx) / s;

    // ---- bottom softmax over 225 columns (8 per lane, last partial) ----
    float vb[8];
    float mxb = -CUDART_INF_F;
#pragma unroll
    for (int k = 0; k < 8; k++) {
        int col = lane + 32 * k;
        if (col < NPC) {
            vb[k] = g_bot_logits[sid * NPC + col] + bb[c * NPC + col];
            mxb = fmaxf(mxb, vb[k]);
        } else vb[k] = -CUDART_INF_F;
    }
#pragma unroll
    for (int o = 16; o > 0; o >>= 1) mxb = fmaxf(mxb, __shfl_xor_sync(0xFFFFFFFFu, mxb, o));
    float sb = 0.f;
#pragma unroll
    for (int k = 0; k < 8; k++) sb += __expf(vb[k] - mxb);
#pragma unroll
    for (int o = 16; o > 0; o >>= 1) sb += __shfl_xor_sync(0xFFFFFFFFu, sb, o);

    int pb = g_pos_bottom[sid];
    if (lane == (pb & 31))
        out[sid] = top_p * (__expf(vb[pb >> 5] - mxb) / sb);
}

// ---------------- launch -----------------------------------------------------
extern "C" void kernel_launch(void* const* d_in, const int* in_sizes, int n_in,
                              void* d_out, int out_size)
{
    const float* X   = (const float*)d_in[0];   // [1024, 1024]
    const void*  lab = d_in[1];                 // [1024] int32/int64
    const float* Wt  = (const float*)d_in[2];   // [1024, 224]
    const float* bt  = (const float*)d_in[3];   // [224]
    const float* Wb  = (const float*)d_in[4];   // [224, 1024, 225]
    const float* bb  = (const float*)d_in[5];   // [224, 225]
    float* out = (float*)d_out;

    k_init<<<112, 1024>>>(lab);
    k_main<<<ALL_BLOCKS, 128>>>(X, Wt, Wb);
    k_finish<<<BATCH / 4, 128>>>(bt, bb, out);
}